// round 17
// baseline (speedup 1.0000x reference)
#include <cuda_runtime.h>
#include <cuda_bf16.h>
#include <cstdint>

#define B_SZ 4096
#define G_NUM 16384
#define D0 4096
#define D1 2048
#define D2 512
#define KEMB 8192

// -------- scratch (static device memory; no allocations) --------
__device__ float g_h1[(size_t)B_SZ * D0];
__device__ float g_h2[(size_t)B_SZ * D1];
__device__ float g_z [(size_t)B_SZ * D2];
__device__ float g_ee[KEMB];
__device__ float g_zz[B_SZ];
__device__ unsigned long long g_best[B_SZ];
__device__ float g_rowsum[B_SZ];

// packed fp16 pairs (u32 = 2 consecutive elements)
__device__ uint32_t g_w4h[(size_t)D1 * D2 / 2];
__device__ uint32_t g_w5h[(size_t)D0 * D1 / 2];
__device__ uint32_t g_w6h[(size_t)G_NUM * D0 / 2];
__device__ uint32_t g_qh [(size_t)B_SZ * D2 / 2];
__device__ uint32_t g_h2h[(size_t)B_SZ * D1 / 2];
__device__ uint32_t g_h1h[(size_t)B_SZ * D0 / 2];

// ---------------- XLA/Eigen tanh f32 rational approximation ----------------
__device__ __forceinline__ float xla_tanh(float x)
{
    if (fabsf(x) < 0.0004f) return x;
    float xc = fminf(fmaxf(x, -7.90531110763549805f), 7.90531110763549805f);
    float x2 = __fmul_rn(xc, xc);
    float p = fmaf(x2, -2.76076847742355e-16f, 2.00018790482477e-13f);
    p = fmaf(x2, p, -8.60467152213735e-11f);
    p = fmaf(x2, p,  5.12229709037114e-08f);
    p = fmaf(x2, p,  1.48572235717979e-05f);
    p = fmaf(x2, p,  6.37261928875436e-04f);
    p = fmaf(x2, p,  4.89352455891786e-03f);
    p = __fmul_rn(xc, p);
    float q = fmaf(x2, 1.19825839466702e-06f, 1.18534705686654e-04f);
    q = fmaf(x2, q, 2.26843463243900e-03f);
    q = fmaf(x2, q, 4.89352518554385e-03f);
    return __fdiv_rn(p, q);
}

// ---------------- packed fp32x2 helpers ----------------
__device__ __forceinline__ void ffma2(unsigned long long& d,
                                      unsigned long long a, unsigned long long b)
{
    asm("fma.rn.f32x2 %0, %1, %2, %0;" : "+l"(d) : "l"(a), "l"(b));
}
__device__ __forceinline__ unsigned long long dup2(float a)
{
    unsigned long long r;
    asm("mov.b64 %0, {%1, %1};" : "=l"(r) : "f"(a));
    return r;
}
__device__ __forceinline__ float2 unpack2(unsigned long long v)
{
    float lo, hi;
    asm("mov.b64 {%0, %1}, %2;" : "=f"(lo), "=f"(hi) : "l"(v));
    return make_float2(lo, hi);
}

// ======================= SIMT exact-chain GEMM (encoder) =======================
__device__ __forceinline__ void sts_tile(float (&As)[16][128], float (&Bs)[16][128],
                                         int lr, int lc,
                                         float4 a0, float4 a1, float4 w0, float4 w1)
{
    As[lc + 0][lr] = a0.x; As[lc + 1][lr] = a0.y;
    As[lc + 2][lr] = a0.z; As[lc + 3][lr] = a0.w;
    As[lc + 8][lr] = a1.x; As[lc + 9][lr] = a1.y;
    As[lc +10][lr] = a1.z; As[lc +11][lr] = a1.w;
    Bs[lc + 0][lr] = w0.x; Bs[lc + 1][lr] = w0.y;
    Bs[lc + 2][lr] = w0.z; Bs[lc + 3][lr] = w0.w;
    Bs[lc + 8][lr] = w1.x; Bs[lc + 9][lr] = w1.y;
    Bs[lc +10][lr] = w1.z; Bs[lc +11][lr] = w1.w;
}

// packed-f32x2 inner product tile; each acc lane keeps its own ascending-k
// IEEE-RN FMA chain (bit-identical to scalar fmaf version).
__device__ __forceinline__ void tile_fma16p(const float (&As)[16][128],
                                            const float (&Bs)[16][128],
                                            unsigned long long (&acc)[8][4],
                                            int tx, int ty)
{
#pragma unroll
    for (int kk = 0; kk < 16; kk++) {
        float4 a0 = *(const float4*)&As[kk][ty * 8];
        float4 a1 = *(const float4*)&As[kk][ty * 8 + 4];
        ulonglong2 b01 = *(const ulonglong2*)&Bs[kk][tx * 4];
        ulonglong2 b23 = *(const ulonglong2*)&Bs[kk][64 + tx * 4];
        unsigned long long bb[4] = {b01.x, b01.y, b23.x, b23.y};
        float a[8] = {a0.x, a0.y, a0.z, a0.w, a1.x, a1.y, a1.z, a1.w};
#pragma unroll
        for (int i = 0; i < 8; i++) {
            unsigned long long ai = dup2(a[i]);
#pragma unroll
            for (int p = 0; p < 4; p++) ffma2(acc[i][p], ai, bb[p]);
        }
    }
}

__device__ __forceinline__ int col_of(int tx, int j)
{
    return (j < 4) ? (tx * 4 + j) : (64 + tx * 4 + (j - 4));
}

__device__ __forceinline__ float (&sub16(float* base, int buf, int half))[16][128]
{
    return *(float (*)[16][128])(base + (size_t)buf * (32 * 128) + (size_t)half * (16 * 128));
}

// 128x128x32 exact-chain SGEMM, dynamic smem 64KB, 2-phase staged loads.
#define ENC_SMEM (2 * 32 * 128 * 2 * 4)   // 65536
template<bool TANH>
__global__ __launch_bounds__(256, 2)
void gemm_bias_act(const float* __restrict__ A, const float* __restrict__ W,
                   const float* __restrict__ bias, float* __restrict__ C,
                   int M, int N, int K)
{
    extern __shared__ float smx[];
    float* Asb = smx;                    // [2][32][128]
    float* Bsb = smx + 2 * 32 * 128;     // [2][32][128]
    const int t  = threadIdx.x;
    const int tx = t & 15, ty = t >> 4;
    const int m0 = blockIdx.y * 128, n0 = blockIdx.x * 128;
    const int lr = t >> 1;
    const int lc = (t & 1) * 4;
    const float* Aptr = A + (size_t)(m0 + lr) * K + lc;
    const float* Wptr = W + (size_t)(n0 + lr) * K + lc;

    unsigned long long acc[8][4];
#pragma unroll
    for (int i = 0; i < 8; i++)
#pragma unroll
        for (int p = 0; p < 4; p++) acc[i][p] = 0ull;

    {
        float4 a0 = *(const float4*)(Aptr);
        float4 a1 = *(const float4*)(Aptr + 8);
        float4 w0 = *(const float4*)(Wptr);
        float4 w1 = *(const float4*)(Wptr + 8);
        sts_tile(sub16(Asb, 0, 0), sub16(Bsb, 0, 0), lr, lc, a0, a1, w0, w1);
        a0 = *(const float4*)(Aptr + 16);
        a1 = *(const float4*)(Aptr + 24);
        w0 = *(const float4*)(Wptr + 16);
        w1 = *(const float4*)(Wptr + 24);
        sts_tile(sub16(Asb, 0, 1), sub16(Bsb, 0, 1), lr, lc, a0, a1, w0, w1);
    }
    __syncthreads();

    int cur = 0;
    for (int k0 = 32; k0 < K; k0 += 32) {
        const int nxt = cur ^ 1;
        float4 a0 = *(const float4*)(Aptr + k0);
        float4 a1 = *(const float4*)(Aptr + k0 + 8);
        float4 w0 = *(const float4*)(Wptr + k0);
        float4 w1 = *(const float4*)(Wptr + k0 + 8);
        tile_fma16p(sub16(Asb, cur, 0), sub16(Bsb, cur, 0), acc, tx, ty);
        sts_tile(sub16(Asb, nxt, 0), sub16(Bsb, nxt, 0), lr, lc, a0, a1, w0, w1);
        a0 = *(const float4*)(Aptr + k0 + 16);
        a1 = *(const float4*)(Aptr + k0 + 24);
        w0 = *(const float4*)(Wptr + k0 + 16);
        w1 = *(const float4*)(Wptr + k0 + 24);
        tile_fma16p(sub16(Asb, cur, 1), sub16(Bsb, cur, 1), acc, tx, ty);
        sts_tile(sub16(Asb, nxt, 1), sub16(Bsb, nxt, 1), lr, lc, a0, a1, w0, w1);
        __syncthreads();
        cur = nxt;
    }
    tile_fma16p(sub16(Asb, cur, 0), sub16(Bsb, cur, 0), acc, tx, ty);
    tile_fma16p(sub16(Asb, cur, 1), sub16(Bsb, cur, 1), acc, tx, ty);

#pragma unroll
    for (int i = 0; i < 8; i++) {
        const int m = m0 + ty * 8 + i;
#pragma unroll
        for (int p = 0; p < 4; p++) {
            float2 pr = unpack2(acc[i][p]);
#pragma unroll
            for (int h = 0; h < 2; h++) {
                const int j = 2 * p + h;
                const int n = n0 + col_of(tx, j);
                float v = __fadd_rn(h ? pr.y : pr.x, bias[n]);
                if (TANH) v = xla_tanh(v);
                C[(size_t)m * N + n] = v;
            }
        }
    }
}

// ======================= conversion helpers =======================
__device__ __forceinline__ uint32_t cvt_h2(float f0, float f1)
{
    uint32_t r;
    asm("cvt.rn.f16x2.f32 %0, %1, %2;" : "=r"(r) : "f"(f1), "f"(f0));
    return r;
}

__global__ void quant_h16(const float* __restrict__ W, uint32_t* __restrict__ Wh, int n4)
{
    int i = blockIdx.x * 256 + threadIdx.x;
    if (i >= n4) return;
    float4 v = ((const float4*)W)[i];
    ((uint2*)Wh)[i] = make_uint2(cvt_h2(v.x, v.y), cvt_h2(v.z, v.w));
}

// ======================= HMMA decoder GEMM (fp16 1-term, cp.async) =======================
__device__ __forceinline__ uint32_t smem_u32(const void* p)
{
    uint32_t a;
    asm("{ .reg .u64 t; cvta.to.shared.u64 t, %1; cvt.u32.u64 %0, t; }"
        : "=r"(a) : "l"(p));
    return a;
}

__device__ __forceinline__ void mma_f16(float* c, const uint32_t* a, const uint32_t* b)
{
    asm volatile(
        "mma.sync.aligned.m16n8k16.row.col.f32.f16.f16.f32 "
        "{%0,%1,%2,%3}, {%4,%5,%6,%7}, {%8,%9}, {%0,%1,%2,%3};"
        : "+f"(c[0]), "+f"(c[1]), "+f"(c[2]), "+f"(c[3])
        : "r"(a[0]), "r"(a[1]), "r"(a[2]), "r"(a[3]), "r"(b[0]), "r"(b[1]));
}

__device__ __forceinline__ void ldmx4(uint32_t* r, uint32_t a)
{
    asm volatile("ldmatrix.sync.aligned.m8n8.x4.shared.b16 {%0,%1,%2,%3}, [%4];"
                 : "=r"(r[0]), "=r"(r[1]), "=r"(r[2]), "=r"(r[3]) : "r"(a));
}
__device__ __forceinline__ void ldmx2(uint32_t* r, uint32_t a)
{
    asm volatile("ldmatrix.sync.aligned.m8n8.x2.shared.b16 {%0,%1}, [%2];"
                 : "=r"(r[0]), "=r"(r[1]) : "r"(a));
}
__device__ __forceinline__ void cp16(uint32_t dst, const void* src)
{
    asm volatile("cp.async.cg.shared.global [%0], [%1], 16;"
                 :: "r"(dst), "l"(src) : "memory");
}
__device__ __forceinline__ void cp_commit()
{
    asm volatile("cp.async.commit_group;" ::: "memory");
}
template<int N_>
__device__ __forceinline__ void cp_wait()
{
    asm volatile("cp.async.wait_group %0;" :: "n"(N_) : "memory");
}

#define HSTRIDE 80
#define HTILE  (128 * HSTRIDE)   // 10240
#define HBUF   (2 * HTILE)       // 20480 (A + B)
#define HSMEM  (3 * HBUF)        // 61440, triple-buffered

// C = act(A @ W^T + bias); packed fp16 inputs, cp.async triple-buffer pipeline.
// Single barrier per slab is safe with 3 buffers: issue(s+1) overwrites the
// buffer last read by compute(s-2), which precedes bar(s-1) in program order.
// OUTMODE 0: fp32 scalar C (x_recon; may be 4B-aligned). OUTMODE 2: fp16 packed Chp.
template<int OUTMODE, bool TANH>
__global__ __launch_bounds__(256, 2)
void gemm_h16(const uint32_t* __restrict__ Ah, const uint32_t* __restrict__ Bh,
              const float* __restrict__ bias, float* __restrict__ C,
              uint32_t* __restrict__ Chp, int N, int K)
{
    extern __shared__ char sm[];
    const uint32_t sb = smem_u32(sm);
    const int t    = threadIdx.x;
    const int lane = t & 31;
    const int wid  = t >> 5;
    const int wm   = (wid >> 2) * 64;
    const int wn   = (wid & 3) * 32;
    const int m0   = blockIdx.x * 128;
    const int n0   = blockIdx.y * 128;
    const int Kp   = K >> 1;

    const int tile = t >> 7, u = t & 127;
    const uint32_t* g = tile ? (Bh + (size_t)(n0 + u) * Kp)
                             : (Ah + (size_t)(m0 + u) * Kp);
    const uint32_t dstr = (uint32_t)(tile * HTILE + u * HSTRIDE);

    float acc[4][4][4];
#pragma unroll
    for (int i = 0; i < 4; i++)
#pragma unroll
        for (int j = 0; j < 4; j++)
#pragma unroll
            for (int r = 0; r < 4; r++) acc[i][j][r] = 0.f;

    const int nslab = K >> 5;

    // prologue: slab 0 in flight
    {
        const uint32_t da = sb + dstr;
#pragma unroll
        for (int c = 0; c < 4; c++) cp16(da + c * 16, g + c * 4);
        cp_commit();
    }

    const uint32_t a_lane = (uint32_t)((wm + (lane & 7) + ((lane >> 3) & 1) * 8) * HSTRIDE
                                       + (lane >> 4) * 16);
    const uint32_t b_lane = (uint32_t)((wn + (lane & 7)) * HSTRIDE
                                       + ((lane >> 3) & 1) * 16);

    for (int s = 0; s < nslab; s++) {
        if (s + 1 < nslab) {
            const uint32_t da = sb + (uint32_t)(((s + 1) % 3) * HBUF) + dstr;
            const uint32_t* gs = g + (s + 1) * 16;
#pragma unroll
            for (int c = 0; c < 4; c++) cp16(da + c * 16, gs + c * 4);
            cp_commit();
            cp_wait<1>();
        } else {
            cp_wait<0>();
        }
        __syncthreads();

        const uint32_t buf = sb + (uint32_t)((s % 3) * HBUF);
        const uint32_t Ath = buf;
        const uint32_t Bth = buf + HTILE;
#pragma unroll
        for (int ks = 0; ks < 2; ks++) {
            uint32_t ah[4][4], bh[4][2];
#pragma unroll
            for (int mt = 0; mt < 4; mt++)
                ldmx4(ah[mt], Ath + a_lane + (uint32_t)(mt * 16 * HSTRIDE + ks * 32));
#pragma unroll
            for (int nt = 0; nt < 4; nt++)
                ldmx2(bh[nt], Bth + b_lane + (uint32_t)(nt * 8 * HSTRIDE + ks * 32));
#pragma unroll
            for (int mt = 0; mt < 4; mt++)
#pragma unroll
                for (int nt = 0; nt < 4; nt++)
                    mma_f16(acc[mt][nt], ah[mt], bh[nt]);
        }
    }

#pragma unroll
    for (int mt = 0; mt < 4; mt++) {
        const int mr = m0 + wm + mt * 16 + (lane >> 2);
#pragma unroll
        for (int nt = 0; nt < 4; nt++) {
            const int nc = n0 + wn + nt * 8 + (lane & 3) * 2;
            float v0 = __fadd_rn(acc[mt][nt][0], bias[nc]);
            float v1 = __fadd_rn(acc[mt][nt][1], bias[nc + 1]);
            float v2 = __fadd_rn(acc[mt][nt][2], bias[nc]);
            float v3 = __fadd_rn(acc[mt][nt][3], bias[nc + 1]);
            if (TANH) { v0 = xla_tanh(v0); v1 = xla_tanh(v1); v2 = xla_tanh(v2); v3 = xla_tanh(v3); }
            if (OUTMODE == 0) {
                float* r0 = &C[(size_t)mr * N + nc];
                float* r1 = &C[(size_t)(mr + 8) * N + nc];
                r0[0] = v0; r0[1] = v1;
                r1[0] = v2; r1[1] = v3;
            } else {
                Chp[(size_t)mr * (N >> 1) + (nc >> 1)]       = cvt_h2(v0, v1);
                Chp[(size_t)(mr + 8) * (N >> 1) + (nc >> 1)] = cvt_h2(v2, v3);
            }
        }
    }
}

// ======================= VQ / misc kernels (bit-exact path) =======================
__global__ void ee_kernel(const float* __restrict__ E)
{
    const int row  = blockIdx.x * 8 + (threadIdx.x >> 5);
    const int lane = threadIdx.x & 31;
    const float* e = E + (size_t)row * D2;
    float s = 0.f;
    for (int j = lane; j < D2; j += 32)
        s = __fadd_rn(s, __fmul_rn(e[j], e[j]));
#pragma unroll
    for (int o = 16; o; o >>= 1) s = __fadd_rn(s, __shfl_xor_sync(0xffffffffu, s, o));
    if (lane == 0) g_ee[row] = s;
}

// zz = sum(z*z, axis=1): coalesced smem staging; per-row chain stays the exact
// sequential k=0..511 ascending order (bit-identical to the validated version).
__global__ void zz_kernel()
{
    __shared__ float buf[256][33];
    const int m0 = blockIdx.x * 256;
    const int t  = threadIdx.x;
    float s = 0.f;
    for (int k0 = 0; k0 < D2; k0 += 32) {
#pragma unroll
        for (int j = 0; j < 32; j++) {
            const int idx = j * 256 + t;
            buf[idx >> 5][idx & 31] =
                g_z[(size_t)(m0 + (idx >> 5)) * D2 + k0 + (idx & 31)];
        }
        __syncthreads();
#pragma unroll
        for (int kk = 0; kk < 32; kk++)
            s = __fadd_rn(s, __fmul_rn(buf[t][kk], buf[t][kk]));
        __syncthreads();
    }
    g_zz[m0 + t] = s;
}

__global__ void init_best()
{
    int i = blockIdx.x * 256 + threadIdx.x;
    if (i < B_SZ) g_best[i] = ~0ull;
}

__device__ __forceinline__ unsigned int orderable_f32(float f)
{
    unsigned int u = __float_as_uint(f);
    return (u & 0x80000000u) ? ~u : (u | 0x80000000u);
}

__global__ __launch_bounds__(256, 2)
void vq_score(const float* __restrict__ Z, const float* __restrict__ E)
{
    __shared__ float As[2][16][128];
    __shared__ float Bs[2][16][128];
    const int t  = threadIdx.x;
    const int tx = t & 15, ty = t >> 4;
    const int m0 = blockIdx.y * 128, n0 = blockIdx.x * 128;
    const int lr = t >> 1;
    const int lc = (t & 1) * 4;
    const float* Aptr = Z + (size_t)(m0 + lr) * D2 + lc;
    const float* Wptr = E + (size_t)(n0 + lr) * D2 + lc;

    unsigned long long acc[8][4];
#pragma unroll
    for (int i = 0; i < 8; i++)
#pragma unroll
        for (int p = 0; p < 4; p++) acc[i][p] = 0ull;

    {
        float4 a0 = *(const float4*)(Aptr);
        float4 a1 = *(const float4*)(Aptr + 8);
        float4 w0 = *(const float4*)(Wptr);
        float4 w1 = *(const float4*)(Wptr + 8);
        sts_tile(As[0], Bs[0], lr, lc, a0, a1, w0, w1);
    }
    __syncthreads();

    int cur = 0;
    for (int k0 = 16; k0 < D2; k0 += 16) {
        float4 a0 = *(const float4*)(Aptr + k0);
        float4 a1 = *(const float4*)(Aptr + k0 + 8);
        float4 w0 = *(const float4*)(Wptr + k0);
        float4 w1 = *(const float4*)(Wptr + k0 + 8);
        tile_fma16p(As[cur], Bs[cur], acc, tx, ty);
        sts_tile(As[cur ^ 1], Bs[cur ^ 1], lr, lc, a0, a1, w0, w1);
        __syncthreads();
        cur ^= 1;
    }
    tile_fma16p(As[cur], Bs[cur], acc, tx, ty);

#pragma unroll
    for (int i = 0; i < 8; i++) {
        const int m = m0 + ty * 8 + i;
        const float zzm = g_zz[m];
        unsigned long long best = ~0ull;
#pragma unroll
        for (int p = 0; p < 4; p++) {
            float2 pr = unpack2(acc[i][p]);
#pragma unroll
            for (int h = 0; h < 2; h++) {
                const int j = 2 * p + h;
                const int n = n0 + col_of(tx, j);
                const float s    = h ? pr.y : pr.x;
                const float zze  = __fadd_rn(zzm, g_ee[n]);
                const float twos = __fmul_rn(2.f, s);
                const float d    = __fadd_rn(zze, -twos);
                unsigned long long key =
                    ((unsigned long long)orderable_f32(d) << 32) | (unsigned int)n;
                best = (key < best) ? key : best;
            }
        }
#pragma unroll
        for (int o = 8; o; o >>= 1) {
            unsigned long long other = __shfl_xor_sync(0xffffffffu, best, o);
            best = (other < best) ? other : best;
        }
        if (tx == 0) atomicMin(&g_best[m], best);
    }
}

__global__ void gather_loss(const float* __restrict__ E, float* __restrict__ out_q)
{
    const int m   = blockIdx.x;
    const int idx = (int)(unsigned int)(g_best[m] & 0xFFFFFFFFull);
    const float* e = E + (size_t)idx * D2;
    const float* z = g_z + (size_t)m * D2;
    const int j = threadIdx.x * 2;
    float q0 = e[j], q1 = e[j + 1];
    float d0 = q0 - z[j], d1 = q1 - z[j + 1];
    float s = fmaf(d1, d1, d0 * d0);
    g_qh[((size_t)m * D2 + j) >> 1] = cvt_h2(q0, q1);
    if (out_q) { out_q[(size_t)m * D2 + j] = q0; out_q[(size_t)m * D2 + j + 1] = q1; }

    __shared__ float red[256];
    red[threadIdx.x] = s;
    __syncthreads();
    for (int o = 128; o; o >>= 1) {
        if (threadIdx.x < o) red[threadIdx.x] += red[threadIdx.x + o];
        __syncthreads();
    }
    if (threadIdx.x == 0) g_rowsum[m] = red[0];
}

__global__ void reduce_loss(float* __restrict__ out_loss)
{
    __shared__ float red[1024];
    float s = 0.f;
    for (int i = threadIdx.x; i < B_SZ; i += 1024) s += g_rowsum[i];
    red[threadIdx.x] = s;
    __syncthreads();
    for (int o = 512; o; o >>= 1) {
        if (threadIdx.x < o) red[threadIdx.x] += red[threadIdx.x + o];
        __syncthreads();
    }
    if (threadIdx.x == 0)
        out_loss[0] = red[0] * (1.25f / (float)((size_t)B_SZ * D2));
}

// ----------------------------------------------------------------
extern "C" void kernel_launch(void* const* d_in, const int* in_sizes, int n_in,
                              void* d_out, int out_size)
{
    const float* X  = (const float*)d_in[0];
    const float* W1 = (const float*)d_in[1];
    const float* b1 = (const float*)d_in[2];
    const float* W2 = (const float*)d_in[3];
    const float* b2 = (const float*)d_in[4];
    const float* W3 = (const float*)d_in[5];
    const float* b3 = (const float*)d_in[6];
    const float* E  = (const float*)d_in[7];
    const float* W4 = (const float*)d_in[8];
    const float* b4 = (const float*)d_in[9];
    const float* W5 = (const float*)d_in[10];
    const float* b5 = (const float*)d_in[11];
    const float* W6 = (const float*)d_in[12];
    const float* b6 = (const float*)d_in[13];

    float *h1, *h2, *z;
    cudaGetSymbolAddress((void**)&h1, g_h1);
    cudaGetSymbolAddress((void**)&h2, g_h2);
    cudaGetSymbolAddress((void**)&z,  g_z);
    uint32_t *w4h, *w5h, *w6h, *qh, *h2h, *h1h;
    cudaGetSymbolAddress((void**)&w4h, g_w4h);
    cudaGetSymbolAddress((void**)&w5h, g_w5h);
    cudaGetSymbolAddress((void**)&w6h, g_w6h);
    cudaGetSymbolAddress((void**)&qh,  g_qh);
    cudaGetSymbolAddress((void**)&h2h, g_h2h);
    cudaGetSymbolAddress((void**)&h1h, g_h1h);

    float* out = (float*)d_out;
    const long long full = 1LL + (long long)B_SZ * G_NUM + (long long)B_SZ * D2;
    float* out_loss = nullptr;
    float* out_x    = out;
    float* out_q    = nullptr;
    if ((long long)out_size == full) {
        out_loss = out;
        out_x    = out + 1;
        out_q    = out + 1 + (long long)B_SZ * G_NUM;
    }

    cudaFuncSetAttribute((const void*)gemm_bias_act<true>,
                         cudaFuncAttributeMaxDynamicSharedMemorySize, ENC_SMEM);
    cudaFuncSetAttribute((const void*)gemm_h16<2, true>,
                         cudaFuncAttributeMaxDynamicSharedMemorySize, HSMEM);
    cudaFuncSetAttribute((const void*)gemm_h16<0, false>,
                         cudaFuncAttributeMaxDynamicSharedMemorySize, HSMEM);

    const dim3 blk(256);

    // weight prep (independent of encoder)
    quant_h16<<<(D1 * D2 / 4 + 255) / 256, 256>>>(W4, w4h, D1 * D2 / 4);
    quant_h16<<<(D0 * D1 / 4 + 255) / 256, 256>>>(W5, w5h, D0 * D1 / 4);
    quant_h16<<<(G_NUM / 4 * D0 + 255) / 256, 256>>>(W6, w6h, G_NUM / 4 * D0);

    ee_kernel<<<KEMB / 8, 256>>>(E);
    init_best<<<B_SZ / 256, 256>>>();

    // encoder (bit-exact fp32 chains; Kt=32 staged double-buffer)
    gemm_bias_act<true><<<dim3(D0 / 128, B_SZ / 128), blk, ENC_SMEM>>>(X,  W1, b1, h1, B_SZ, D0, G_NUM);
    gemm_bias_act<true><<<dim3(D1 / 128, B_SZ / 128), blk, ENC_SMEM>>>(h1, W2, b2, h2, B_SZ, D1, D0);
    gemm_bias_act<true><<<dim3(D2 / 128, B_SZ / 128), blk, ENC_SMEM>>>(h2, W3, b3, z,  B_SZ, D2, D1);

    // VQ (bit-exact replication of reference dist formula)
    zz_kernel<<<B_SZ / 256, 256>>>();
    vq_score<<<dim3(KEMB / 128, B_SZ / 128), blk>>>(z, E);
    gather_loss<<<B_SZ, 256>>>(E, out_q);
    if (out_loss) reduce_loss<<<1, 1024>>>(out_loss);

    // decoder: fp16 1-term HMMA with cp.async triple-buffer pipeline
    gemm_h16<2, true ><<<dim3(B_SZ / 128, D1 / 128),    blk, HSMEM>>>(
        qh, w4h, b4, nullptr, h2h, D1, D2);
    gemm_h16<2, true ><<<dim3(B_SZ / 128, D0 / 128),    blk, HSMEM>>>(
        h2h, w5h, b5, nullptr, h1h, D0, D1);
    gemm_h16<0, false><<<dim3(B_SZ / 128, G_NUM / 128), blk, HSMEM>>>(
        h1h, w6h, b6, out_x, nullptr, G_NUM, D0);
}